// round 5
// baseline (speedup 1.0000x reference)
#include <cuda_runtime.h>
#include <math.h>
#include <stdint.h>

// ---------------------------------------------------------------------------
// DiffAttention  B=1 S=2048 HID=2048 H=16 KVH=8 HD=128
// tf32 tensor cores: ldmatrix + SW128 swizzle + cp.async, BK=32, 3 stages.
// Q/QN and K/KN packed side-by-side -> single batched score GEMM (z=0..31).
// ---------------------------------------------------------------------------
namespace {
constexpr int S_LEN   = 2048;
constexpr int NH      = 16;
constexpr int NKV     = 8;
constexpr int DH      = 128;
constexpr float ATT_SCALE = 0.08838834764831845f;   // 128^-0.5
constexpr float LAM0      = 0.2f;
constexpr float EPSV      = 1e-5f;
constexpr long long ATTN_ELEMS = (long long)NH * S_LEN * S_LEN;   // 67108864
constexpr long long OUT_ELEMS  = (long long)S_LEN * (NH * DH);    // 4194304

constexpr int BK         = 32;
constexpr int TILE_BYTES = 128 * BK * 4;      // 16KB (128 rows x 128B)
constexpr int STG_BYTES  = 2 * TILE_BYTES;    // A + B per stage: 32KB
constexpr int NSTAGE     = 3;
constexpr int SMEM_BYTES = NSTAGE * STG_BYTES;   // 98304
}

// scratch (device globals: allocation-free contract)
__device__ float g_QQN[S_LEN * 4096];            // [s, Q(32h x128) | QN]
__device__ float g_KKN[S_LEN * 2048];            // [s, K(8h x128) | KN]
__device__ float g_V  [S_LEN * NKV * 2 * DH];
__device__ float g_Vt [S_LEN * NKV * 2 * DH];    // V transposed, tf32-rounded
__device__ float g_sc [(long long)32 * S_LEN * S_LEN];  // aw: z0-15, an: z16-31
__device__ float g_o  [NH * S_LEN * 2 * DH];
__device__ float g_y  [S_LEN * NH * 2 * DH];
__device__ float g_lam[NH];
__device__ float g_mu[2 * NH];
__device__ float g_rstd[2 * NH];
// tf32-rounded copies of harness inputs
__device__ float g_Xr  [S_LEN * 2048];
__device__ float g_Wqr [NH  * DH * 2048];
__device__ float g_Wkr [NKV * DH * 2048];
__device__ float g_Wqnr[NH  * DH * 2048];
__device__ float g_Wknr[NKV * DH * 2048];
__device__ float g_Wvr [2 * NKV * DH * 2048];
__device__ float g_Wor [NH * DH * 4096];

// ---------------------------------------------------------------------------
// helpers
// ---------------------------------------------------------------------------
__device__ __forceinline__ float rnd_tf32(float x) {
    uint32_t r;
    asm("cvt.rna.tf32.f32 %0, %1;" : "=r"(r) : "f"(x));
    return __uint_as_float(r);
}
__device__ __forceinline__ void mma_tf32(float* c, const uint32_t* a, const uint32_t* b) {
    asm volatile(
        "mma.sync.aligned.m16n8k8.row.col.f32.tf32.tf32.f32 "
        "{%0,%1,%2,%3}, {%4,%5,%6,%7}, {%8,%9}, {%0,%1,%2,%3};\n"
        : "+f"(c[0]), "+f"(c[1]), "+f"(c[2]), "+f"(c[3])
        : "r"(a[0]), "r"(a[1]), "r"(a[2]), "r"(a[3]),
          "r"(b[0]), "r"(b[1]));
}
__device__ __forceinline__ void cp_async16(uint32_t saddr, const float* gptr) {
    asm volatile("cp.async.ca.shared.global [%0], [%1], 16;\n"
                 :: "r"(saddr), "l"(gptr));
}
__device__ __forceinline__ void ldsm4(uint32_t& d0, uint32_t& d1,
                                      uint32_t& d2, uint32_t& d3, uint32_t addr) {
    asm volatile("ldmatrix.sync.aligned.m8n8.x4.shared.b16 {%0,%1,%2,%3}, [%4];"
                 : "=r"(d0), "=r"(d1), "=r"(d2), "=r"(d3) : "r"(addr));
}
// SW128 swizzled byte offset in a 128 x BK(32f=128B) tile
__device__ __forceinline__ uint32_t soff(int r, int c) {
    return (uint32_t)((r << 7) + ((c << 2) ^ ((r & 7) << 4)));
}

// ---------------------------------------------------------------------------
// Tensor-core GEMM NT:  C[m,n] = alpha * sum_k A[m,k]*B[n,k] + bias[n]
// A: [M,K] k-contig (lda), B: [N,K] k-contig (ldb), PRE-ROUNDED tf32.
// Batched: A += z*sA, B += (z>>zshB)*sB, C += z*sC.
// Block 128x128, BK=32, 8 warps (2x4), warp tile 64x32 (4x4 m16n8k8).
// ldmatrix from SW128-swizzled smem, 3-stage cp.async pipeline.
// M,N multiples of 128; K multiple of 32.
// ---------------------------------------------------------------------------
__global__ void __launch_bounds__(256, 2) tgemm_nt(
    const float* __restrict__ A, const float* __restrict__ B,
    const float* __restrict__ bias, float* __restrict__ C,
    int K, int lda, int ldb, int ldc,
    long long sA, long long sB, int zshB, long long sC, float alpha)
{
    extern __shared__ float sm[];

    const int z = blockIdx.z;
    A += (long long)z * sA;
    B += (long long)(z >> zshB) * sB;
    C += (long long)z * sC;
    const int m0 = blockIdx.y << 7, n0 = blockIdx.x << 7;
    const int tid  = threadIdx.x;
    const int wid  = tid >> 5, lane = tid & 31;
    const int wm   = (wid & 1) << 6;        // warp m offset: 0 / 64
    const int wn   = (wid >> 1) << 5;       // warp n offset: 0..96
    const int gid  = lane >> 2, tig = lane & 3;

    // staging: each thread does 4x16B of A and 4x16B of B per 128x32 tile
    const int srow  = tid >> 1;             // 0..127
    const int scol0 = (tid & 1) << 4;       // 0 / 16
    const float* Ag = A + (long long)(m0 + srow) * lda + scol0;
    const float* Bg = B + (long long)(n0 + srow) * ldb + scol0;

    const uint32_t smBase = (uint32_t)__cvta_generic_to_shared(sm);
    const uint32_t st0 = soff(srow, scol0);       // 16B-aligned; +4 cols = ^/+16B
    // ldmatrix base offsets; per-kk advance is XOR (kk<<2)
    const int sub = lane >> 3, li = lane & 7;
    const uint32_t aRel = soff(wm + ((sub & 1) << 3) + li, (sub >> 1) << 2);
    const uint32_t bRel = soff(wn + ((sub >> 1) << 3) + li, (sub & 1) << 2);

    float acc[4][4][4];
#pragma unroll
    for (int i = 0; i < 4; ++i)
#pragma unroll
        for (int j = 0; j < 4; ++j)
#pragma unroll
            for (int v = 0; v < 4; ++v) acc[i][j][v] = 0.f;

    const int T = K / BK;

    // prologue: fill stages 0..NSTAGE-2
#pragma unroll
    for (int s = 0; s < NSTAGE - 1; ++s) {
        if (s < T) {
            const uint32_t off = smBase + s * STG_BYTES;
            const float* Ap = Ag + s * BK;
            const float* Bp = Bg + s * BK;
#pragma unroll
            for (int i = 0; i < 4; ++i) {
                const uint32_t d = st0 ^ (uint32_t)(i << 4);
                cp_async16(off + d, Ap + (i << 2));
                cp_async16(off + TILE_BYTES + d, Bp + (i << 2));
            }
        }
        asm volatile("cp.async.commit_group;\n" ::);
    }

    int ldS = 0, ldN = NSTAGE - 1;
    for (int t = 0; t < T; ++t) {
        asm volatile("cp.async.wait_group %0;\n" :: "n"(NSTAGE - 2));
        __syncthreads();

        if (t + NSTAGE - 1 < T) {
            const uint32_t off = smBase + ldN * STG_BYTES;
            const float* Ap = Ag + (t + NSTAGE - 1) * BK;
            const float* Bp = Bg + (t + NSTAGE - 1) * BK;
#pragma unroll
            for (int i = 0; i < 4; ++i) {
                const uint32_t d = st0 ^ (uint32_t)(i << 4);
                cp_async16(off + d, Ap + (i << 2));
                cp_async16(off + TILE_BYTES + d, Bp + (i << 2));
            }
        }
        asm volatile("cp.async.commit_group;\n" ::);
        if (++ldN == NSTAGE) ldN = 0;

        const uint32_t stOff = smBase + ldS * STG_BYTES;
#pragma unroll
        for (int kk = 0; kk < BK; kk += 8) {
            const uint32_t kx = (uint32_t)(kk << 2);
            uint32_t a[4][4], b[4][2];
#pragma unroll
            for (int mt = 0; mt < 4; ++mt)
                ldsm4(a[mt][0], a[mt][1], a[mt][2], a[mt][3],
                      stOff + mt * 2048 + (aRel ^ kx));
#pragma unroll
            for (int j = 0; j < 2; ++j)
                ldsm4(b[2*j][0], b[2*j][1], b[2*j+1][0], b[2*j+1][1],
                      stOff + TILE_BYTES + j * 2048 + (bRel ^ kx));
#pragma unroll
            for (int mt = 0; mt < 4; ++mt)
#pragma unroll
                for (int nt = 0; nt < 4; ++nt)
                    mma_tf32(acc[mt][nt], a[mt], b[nt]);
        }
        if (++ldS == NSTAGE) ldS = 0;
    }

    // epilogue
#pragma unroll
    for (int nt = 0; nt < 4; ++nt) {
        const int c0 = n0 + wn + (nt << 3) + (tig << 1);
        const float b0 = bias ? bias[c0]     : 0.f;
        const float b1 = bias ? bias[c0 + 1] : 0.f;
#pragma unroll
        for (int mt = 0; mt < 4; ++mt) {
            const int r = m0 + wm + (mt << 4) + gid;
            float2 v;
            v.x = acc[mt][nt][0] * alpha + b0;
            v.y = acc[mt][nt][1] * alpha + b1;
            *(float2*)&C[(long long)r * ldc + c0] = v;
            v.x = acc[mt][nt][2] * alpha + b0;
            v.y = acc[mt][nt][3] * alpha + b1;
            *(float2*)&C[(long long)(r + 8) * ldc + c0] = v;
        }
    }
}

// ---------------------------------------------------------------------------
// merged tf32 rounding over all 7 input tensors (table-driven)
// ---------------------------------------------------------------------------
struct RCopy {
    const float4* src[7];
    float4*       dst[7];
    long long     cum[8];
};
__global__ void round_copy_multi(RCopy rc)
{
    long long i = (long long)blockIdx.x * 256 + threadIdx.x;
    if (i >= rc.cum[7]) return;
    int s = 0;
#pragma unroll
    for (int k = 0; k < 6; ++k) if (i >= rc.cum[k + 1]) s = k + 1;
    float4 v = rc.src[s][i - rc.cum[s]];
    v.x = rnd_tf32(v.x); v.y = rnd_tf32(v.y);
    v.z = rnd_tf32(v.z); v.w = rnd_tf32(v.w);
    rc.dst[s][i - rc.cum[s]] = v;
}

// ---------------------------------------------------------------------------
// 2048x2048 transpose, tf32-rounded output (V -> Vt so PV GEMM is NT)
// ---------------------------------------------------------------------------
__global__ void transpose2048(const float* __restrict__ in, float* __restrict__ out)
{
    __shared__ float tile[32][33];
    int x = blockIdx.x * 32 + threadIdx.x;
    int y = blockIdx.y * 32 + threadIdx.y;
#pragma unroll
    for (int i = 0; i < 32; i += 8)
        tile[threadIdx.y + i][threadIdx.x] = in[(long long)(y + i) * 2048 + x];
    __syncthreads();
    x = blockIdx.y * 32 + threadIdx.x;
    y = blockIdx.x * 32 + threadIdx.y;
#pragma unroll
    for (int i = 0; i < 32; i += 8)
        out[(long long)(y + i) * 2048 + x] = rnd_tf32(tile[threadIdx.x][threadIdx.y + i]);
}

// ---------------------------------------------------------------------------
// RoPE in place on [S, HH, 128]; pair (d, d+64); tf32-rounded output
// ---------------------------------------------------------------------------
__global__ void rope_kernel(float* __restrict__ Xv,
                            const float* __restrict__ cs,
                            const float* __restrict__ sn, int HH)
{
    int idx = blockIdx.x * 256 + threadIdx.x;
    int total = S_LEN * HH * 64;
    if (idx >= total) return;
    int d = idx & 63;
    int h = (idx >> 6) % HH;
    int s = idx / (HH * 64);
    float c0 = cs[s * DH + d],       s0 = sn[s * DH + d];
    float c1 = cs[s * DH + 64 + d],  s1 = sn[s * DH + 64 + d];
    long long base = ((long long)s * HH + h) * DH;
    float x0 = Xv[base + d], x1 = Xv[base + 64 + d];
    Xv[base + d]      = rnd_tf32(x0 * c0 - x1 * s0);
    Xv[base + 64 + d] = rnd_tf32(x1 * c1 + x0 * s1);
}

// lam[h] = exp(dot(lq1,lk1)) - exp(dot(lq2,lk2)) + 0.2
__global__ void lam_kernel(const float* __restrict__ lq1, const float* __restrict__ lk1,
                           const float* __restrict__ lq2, const float* __restrict__ lk2)
{
    int h = blockIdx.x, t = threadIdx.x;
    float a = lq1[h * DH + t] * lk1[h * DH + t];
    float b = lq2[h * DH + t] * lk2[h * DH + t];
#pragma unroll
    for (int o = 16; o; o >>= 1) {
        a += __shfl_xor_sync(0xffffffffu, a, o);
        b += __shfl_xor_sync(0xffffffffu, b, o);
    }
    __shared__ float sa[4], sb[4];
    if ((t & 31) == 0) { sa[t >> 5] = a; sb[t >> 5] = b; }
    __syncthreads();
    if (t == 0) {
        float A = sa[0] + sa[1] + sa[2] + sa[3];
        float B = sb[0] + sb[1] + sb[2] + sb[3];
        g_lam[h] = expf(A) - expf(B) + LAM0;
    }
}

// attn = softmax(sc[h]) - lam[h]*softmax(sc[16+h]); tf32-rounded.
__global__ void __launch_bounds__(256) softmax_combine(
    const float* __restrict__ sc, float* __restrict__ attn)
{
    const int q = blockIdx.x, h = blockIdx.y;
    const long long off = ((long long)h * S_LEN + q) * S_LEN;
    const float* r1 = sc + off;
    const float* r2 = sc + off + (long long)16 * S_LEN * S_LEN;
    const int t = threadIdx.x;
    float v1[8], v2[8];
    float m1 = -1e30f, m2 = -1e30f;
#pragma unroll
    for (int i = 0; i < 8; ++i) {
        v1[i] = r1[t + (i << 8)];
        v2[i] = r2[t + (i << 8)];
        m1 = fmaxf(m1, v1[i]);
        m2 = fmaxf(m2, v2[i]);
    }
    __shared__ float sm1[8], sm2[8];
#pragma unroll
    for (int o = 16; o; o >>= 1) {
        m1 = fmaxf(m1, __shfl_xor_sync(0xffffffffu, m1, o));
        m2 = fmaxf(m2, __shfl_xor_sync(0xffffffffu, m2, o));
    }
    if ((t & 31) == 0) { sm1[t >> 5] = m1; sm2[t >> 5] = m2; }
    __syncthreads();
    m1 = sm1[0]; m2 = sm2[0];
#pragma unroll
    for (int i = 1; i < 8; ++i) { m1 = fmaxf(m1, sm1[i]); m2 = fmaxf(m2, sm2[i]); }
    float s1 = 0.f, s2 = 0.f;
#pragma unroll
    for (int i = 0; i < 8; ++i) {
        v1[i] = expf(v1[i] - m1); s1 += v1[i];
        v2[i] = expf(v2[i] - m2); s2 += v2[i];
    }
#pragma unroll
    for (int o = 16; o; o >>= 1) {
        s1 += __shfl_xor_sync(0xffffffffu, s1, o);
        s2 += __shfl_xor_sync(0xffffffffu, s2, o);
    }
    __syncthreads();
    if ((t & 31) == 0) { sm1[t >> 5] = s1; sm2[t >> 5] = s2; }
    __syncthreads();
    s1 = 0.f; s2 = 0.f;
#pragma unroll
    for (int i = 0; i < 8; ++i) { s1 += sm1[i]; s2 += sm2[i]; }
    const float i1 = 1.f / s1;
    const float i2 = g_lam[h] / s2;
    float* w = attn + off;
#pragma unroll
    for (int i = 0; i < 8; ++i)
        w[t + (i << 8)] = rnd_tf32(v1[i] * i1 - v2[i] * i2);
}

// group g = h*2 + (q>=1024): contiguous 262144-float block of g_o
__global__ void group_stats_kernel(const float* __restrict__ ob)
{
    const int g = blockIdx.x;
    const float4* p = (const float4*)(ob + (long long)g * 262144);
    float s = 0.f, ss = 0.f;
    for (int i = threadIdx.x; i < 65536; i += 1024) {
        float4 v = p[i];
        s  += v.x + v.y + v.z + v.w;
        ss += v.x * v.x + v.y * v.y + v.z * v.z + v.w * v.w;
    }
    __shared__ float sa[32], sb[32];
    int t = threadIdx.x;
#pragma unroll
    for (int o = 16; o; o >>= 1) {
        s  += __shfl_xor_sync(0xffffffffu, s, o);
        ss += __shfl_xor_sync(0xffffffffu, ss, o);
    }
    if ((t & 31) == 0) { sa[t >> 5] = s; sb[t >> 5] = ss; }
    __syncthreads();
    if (t < 32) {
        s = sa[t]; ss = sb[t];
#pragma unroll
        for (int o = 16; o; o >>= 1) {
            s  += __shfl_xor_sync(0xffffffffu, s, o);
            ss += __shfl_xor_sync(0xffffffffu, ss, o);
        }
        if (t == 0) {
            float mu  = s * (1.f / 262144.f);
            float var = ss * (1.f / 262144.f) - mu * mu;
            g_mu[g]   = mu;
            g_rstd[g] = rsqrtf(var + EPSV);
        }
    }
}

// y_flat[q, h*256+d] = tf32(((o-mu)*rstd*gamma[r]+beta[r]) * 0.8), r=(q%1024)>>3
__global__ void apply_norm_kernel(const float* __restrict__ ob,
                                  const float* __restrict__ gamma,
                                  const float* __restrict__ beta,
                                  float* __restrict__ y)
{
    int idx = blockIdx.x * 256 + threadIdx.x;      // over 16*2048*256 = 8388608
    int d = idx & 255;
    int q = (idx >> 8) & 2047;
    int h = idx >> 19;
    int g = (h << 1) + (q >> 10);
    int r = (q & 1023) >> 3;
    float v = (ob[idx] - g_mu[g]) * g_rstd[g] * gamma[r] + beta[r];
    y[((long long)q << 12) + (h << 8) + d] = rnd_tf32(v * 0.8f);
}

// ---------------------------------------------------------------------------
extern "C" void kernel_launch(void* const* d_in, const int* in_sizes, int n_in,
                              void* d_out, int out_size)
{
    const float* X    = (const float*)d_in[0];
    const float* cs   = (const float*)d_in[1];
    const float* sn   = (const float*)d_in[2];
    const float* Wq   = (const float*)d_in[3];
    const float* bq   = (const float*)d_in[4];
    const float* Wk   = (const float*)d_in[5];
    const float* bk   = (const float*)d_in[6];
    const float* Wqn  = (const float*)d_in[7];
    const float* bqn  = (const float*)d_in[8];
    const float* Wkn  = (const float*)d_in[9];
    const float* bkn  = (const float*)d_in[10];
    const float* Wv   = (const float*)d_in[11];
    const float* bv   = (const float*)d_in[12];
    const float* Wo   = (const float*)d_in[13];
    const float* bo   = (const float*)d_in[14];
    const float* lq1  = (const float*)d_in[15];
    const float* lk1  = (const float*)d_in[16];
    const float* lq2  = (const float*)d_in[17];
    const float* lk2  = (const float*)d_in[18];
    const float* gam  = (const float*)d_in[19];
    const float* bet  = (const float*)d_in[20];

    float *pQQN, *pKKN, *pV, *pVt, *psc, *po, *py;
    float *pXr, *pWqr, *pWkr, *pWqnr, *pWknr, *pWvr, *pWor;
    cudaGetSymbolAddress((void**)&pQQN, g_QQN);
    cudaGetSymbolAddress((void**)&pKKN, g_KKN);
    cudaGetSymbolAddress((void**)&pV,   g_V);
    cudaGetSymbolAddress((void**)&pVt,  g_Vt);
    cudaGetSymbolAddress((void**)&psc,  g_sc);
    cudaGetSymbolAddress((void**)&po,   g_o);
    cudaGetSymbolAddress((void**)&py,   g_y);
    cudaGetSymbolAddress((void**)&pXr,   g_Xr);
    cudaGetSymbolAddress((void**)&pWqr,  g_Wqr);
    cudaGetSymbolAddress((void**)&pWkr,  g_Wkr);
    cudaGetSymbolAddress((void**)&pWqnr, g_Wqnr);
    cudaGetSymbolAddress((void**)&pWknr, g_Wknr);
    cudaGetSymbolAddress((void**)&pWvr,  g_Wvr);
    cudaGetSymbolAddress((void**)&pWor,  g_Wor);

    float* outp  = (float*)d_out;
    float* attnp = ((long long)out_size >= OUT_ELEMS + ATTN_ELEMS)
                       ? (outp + OUT_ELEMS) : psc;   // reuse aw block if not output

    cudaFuncSetAttribute(tgemm_nt, cudaFuncAttributeMaxDynamicSharedMemorySize,
                         SMEM_BYTES);

    // 0. tf32 rounding of inputs (single merged kernel)
    {
        RCopy rc;
        const float* srcs[7] = {X, Wq, Wk, Wqn, Wkn, Wv, Wo};
        float*       dsts[7] = {pXr, pWqr, pWkr, pWqnr, pWknr, pWvr, pWor};
        long long    cnts[7] = {1048576, 1048576, 524288, 1048576, 524288,
                                2097152, 2097152};   // float4 counts
        rc.cum[0] = 0;
        for (int i = 0; i < 7; ++i) {
            rc.src[i] = (const float4*)srcs[i];
            rc.dst[i] = (float4*)dsts[i];
            rc.cum[i + 1] = rc.cum[i] + cnts[i];
        }
        round_copy_multi<<<(unsigned)((rc.cum[7] + 255) / 256), 256>>>(rc);
    }

    // 1. projections into packed buffers
    tgemm_nt<<<dim3(16,16,1), 256, SMEM_BYTES>>>(pXr, pWqr,  bq,  pQQN,        2048, 2048, 2048, 4096, 0,0,0,0, 1.f);
    tgemm_nt<<<dim3(16,16,1), 256, SMEM_BYTES>>>(pXr, pWqnr, bqn, pQQN + 2048, 2048, 2048, 2048, 4096, 0,0,0,0, 1.f);
    tgemm_nt<<<dim3( 8,16,1), 256, SMEM_BYTES>>>(pXr, pWkr,  bk,  pKKN,        2048, 2048, 2048, 2048, 0,0,0,0, 1.f);
    tgemm_nt<<<dim3( 8,16,1), 256, SMEM_BYTES>>>(pXr, pWknr, bkn, pKKN + 1024, 2048, 2048, 2048, 2048, 0,0,0,0, 1.f);
    tgemm_nt<<<dim3(16,16,1), 256, SMEM_BYTES>>>(pXr, pWvr,  bv,  pV,          2048, 2048, 2048, 2048, 0,0,0,0, 1.f);

    // 2. V transpose (rounded), RoPE over packed buffers, lambda
    transpose2048<<<dim3(64,64), dim3(32,8)>>>(pV, pVt);
    rope_kernel<<<(S_LEN*32*64)/256, 256>>>(pQQN, cs, sn, 32);
    rope_kernel<<<(S_LEN*16*64)/256, 256>>>(pKKN, cs, sn, 16);
    lam_kernel<<<16, 128>>>(lq1, lk1, lq2, lk2);

    // 3. scores: ONE launch, z=0..31 (aw: z<16 from Q/K, an: z>=16 from QN/KN)
    //    A offset z*128 walks Q then QN halves; B offset (z>>1)*128 walks K then KN.
    tgemm_nt<<<dim3(16,16,32), 256, SMEM_BYTES>>>(pQQN, pKKN, nullptr, psc,
                                     128, 4096, 2048, 2048,
                                     128, 128, 1, (long long)S_LEN*S_LEN, ATT_SCALE);

    // 4. attn = softmax(aw) - lam*softmax(an)
    softmax_combine<<<dim3(S_LEN, NH), 256>>>(psc, attnp);

    // 5. out = attn @ Vt^T
    tgemm_nt<<<dim3(2,16,16), 256, SMEM_BYTES>>>(attnp, pVt, nullptr, po,
                                     2048, 2048, 2048, 256,
                                     (long long)S_LEN*S_LEN, (long long)256*2048, 1,
                                     (long long)S_LEN*256, 1.f);

    // 6. group stats + normalize/scatter into y_flat [2048, 4096]
    group_stats_kernel<<<32, 1024>>>(po);
    apply_norm_kernel<<<(16*2048*256)/256, 256>>>(po, gam, bet, py);

    // 7. output = y @ Wo^T + bo
    tgemm_nt<<<dim3(16,16,1), 256, SMEM_BYTES>>>(py, pWor, bo, outp,
                                     4096, 4096, 4096, 2048, 0,0,0,0, 1.f);
}